// round 6
// baseline (speedup 1.0000x reference)
#include <cuda_runtime.h>
#include <cuda_bf16.h>

// ROI pooling (crop + 7x7 bilinear resize), NHWC.
// img:  (1, 128, 128, 1024) fp32
// rois: (1, 1000, 4) int32  -> {x, y, w, h}
// out:  (1, 1000, 7, 7, 1024) fp32
//
// One CTA per (roi, py); 256 threads x float4 covers C=1024.
// Per-px offsets/weights staged in SMEM (uniform) to cut register pressure;
// one-px load lookahead keeps 8 loads in flight per thread.

#define H_IMG 128
#define W_IMG 128
#define C_IMG 1024
#define POOL 7
#define NUM_ROIS 1000
#define CPP (C_IMG / 4)   // float4s per pixel = 256

__global__ __launch_bounds__(256, 5)
void roi_pool_kernel(const float* __restrict__ img,
                     const int*   __restrict__ rois,
                     float*       __restrict__ out)
{
    __shared__ int   s_o0[POOL];
    __shared__ int   s_o1[POOL];
    __shared__ float s_w00[POOL];
    __shared__ float s_w01[POOL];
    __shared__ float s_w10[POOL];
    __shared__ float s_w11[POOL];
    __shared__ int   s_rowoff0, s_rowoff1;

    const int b  = blockIdx.x;            // 0 .. 6999
    const int py = b % POOL;
    const int r  = b / POOL;
    const int c4 = threadIdx.x;           // float4 channel index, 0..255

    if (threadIdx.x < POOL) {
        const int4 roi = __ldg(((const int4*)rois) + r);
        const int rx = roi.x, ry = roi.y, rw = roi.z, rh = roi.w;

        // y axis
        const float hf = (float)rh;
        float fy = (py + 0.5f) * (hf * (1.0f / POOL)) - 0.5f;
        fy = fminf(fmaxf(fy, 0.0f), fmaxf(hf - 1.0f, 0.0f));
        int   iy0 = (int)floorf(fy);
        const float wy  = fy - (float)iy0;
        const float wy1 = 1.0f - wy;
        int   iy1 = min(iy0 + 1, rh - 1);
        if (threadIdx.x == 0) {
            s_rowoff0 = (ry + iy0) * W_IMG * CPP;
            s_rowoff1 = (ry + iy1) * W_IMG * CPP;
        }

        // x axis for this thread's px
        const int px = threadIdx.x;
        const float wf  = (float)rw;
        float fx = (px + 0.5f) * (wf * (1.0f / POOL)) - 0.5f;
        fx = fminf(fmaxf(fx, 0.0f), fmaxf(wf - 1.0f, 0.0f));
        int   ix0 = (int)floorf(fx);
        const float wx  = fx - (float)ix0;
        const float wx1 = 1.0f - wx;
        int   ix1 = min(ix0 + 1, rw - 1);
        s_o0[px]  = (rx + ix0) * CPP;
        s_o1[px]  = (rx + ix1) * CPP;
        s_w00[px] = wx1 * wy1;
        s_w01[px] = wx  * wy1;
        s_w10[px] = wx1 * wy;
        s_w11[px] = wx  * wy;
    }
    __syncthreads();

    const float4* __restrict__ row0 = (const float4*)img + s_rowoff0 + c4;
    const float4* __restrict__ row1 = (const float4*)img + s_rowoff1 + c4;
    float4* __restrict__ optr =
        (float4*)out + ((size_t)(r * POOL + py) * POOL) * CPP + c4;

    // Software-pipelined px loop: loads for px+1 issue before math of px.
    int o0 = s_o0[0], o1 = s_o1[0];
    float4 v00 = __ldg(row0 + o0);
    float4 v01 = __ldg(row0 + o1);
    float4 v10 = __ldg(row1 + o0);
    float4 v11 = __ldg(row1 + o1);

    #pragma unroll
    for (int px = 0; px < POOL; ++px) {
        float4 n00, n01, n10, n11;
        if (px + 1 < POOL) {
            const int p0 = s_o0[px + 1], p1 = s_o1[px + 1];
            n00 = __ldg(row0 + p0);
            n01 = __ldg(row0 + p1);
            n10 = __ldg(row1 + p0);
            n11 = __ldg(row1 + p1);
        }

        const float a = s_w00[px], bb = s_w01[px];
        const float c = s_w10[px], d  = s_w11[px];
        float4 o;
        o.x = v00.x * a + v01.x * bb + v10.x * c + v11.x * d;
        o.y = v00.y * a + v01.y * bb + v10.y * c + v11.y * d;
        o.z = v00.z * a + v01.z * bb + v10.z * c + v11.z * d;
        o.w = v00.w * a + v01.w * bb + v10.w * c + v11.w * d;

        __stcs(optr + (size_t)px * CPP, o);

        v00 = n00; v01 = n01; v10 = n10; v11 = n11;
    }
}

extern "C" void kernel_launch(void* const* d_in, const int* in_sizes, int n_in,
                              void* d_out, int out_size)
{
    const float* img  = (const float*)d_in[0];
    const int*   rois = (const int*)d_in[1];
    float*       out  = (float*)d_out;

    dim3 grid(NUM_ROIS * POOL);
    dim3 block(256);
    roi_pool_kernel<<<grid, block>>>(img, rois, out);
}

// round 7
// speedup vs baseline: 1.0985x; 1.0985x over previous
#include <cuda_runtime.h>
#include <cuda_bf16.h>

// ROI pooling (crop + 7x7 bilinear resize), NHWC.
// img:  (1, 128, 128, 1024) fp32
// rois: (1, 1000, 4) int32  -> {x, y, w, h}
// out:  (1, 1000, 7, 7, 1024) fp32
//
// One CTA per (roi, py); 256 threads x float4 covers C=1024.
// One-px load lookahead with coords computed inline (register-resident
// addresses, minimal live set) -> 5 CTAs/SM at full load-pipeline depth.

#define H_IMG 128
#define W_IMG 128
#define C_IMG 1024
#define POOL 7
#define NUM_ROIS 1000
#define CPP (C_IMG / 4)   // float4s per pixel = 256

__device__ __forceinline__
void xcoords(int px, float sfx, float xcl, int rx, int rw,
             int& off0, int& off1, float& wx)
{
    float fx = (px + 0.5f) * sfx - 0.5f;
    fx = fminf(fmaxf(fx, 0.0f), xcl);
    int ix0 = (int)floorf(fx);
    wx = fx - (float)ix0;
    int ix1 = min(ix0 + 1, rw - 1);
    off0 = (rx + ix0) * CPP;
    off1 = (rx + ix1) * CPP;
}

__global__ __launch_bounds__(256, 5)
void roi_pool_kernel(const float* __restrict__ img,
                     const int*   __restrict__ rois,
                     float*       __restrict__ out)
{
    const int b  = blockIdx.x;            // 0 .. 6999
    const int py = b % POOL;
    const int r  = b / POOL;
    const int c4 = threadIdx.x;           // float4 channel index, 0..255

    const int4 roi = __ldg(((const int4*)rois) + r);
    const int rx = roi.x, ry = roi.y, rw = roi.z, rh = roi.w;

    // y axis (uniform across CTA)
    const float hf = (float)rh;
    float fy = (py + 0.5f) * (hf * (1.0f / POOL)) - 0.5f;
    fy = fminf(fmaxf(fy, 0.0f), fmaxf(hf - 1.0f, 0.0f));
    int   iy0 = (int)floorf(fy);
    const float wy  = fy - (float)iy0;
    const float wy1 = 1.0f - wy;
    int   iy1 = min(iy0 + 1, rh - 1);
    iy0 += ry;  iy1 += ry;

    const float4* __restrict__ row0 =
        (const float4*)(img + ((size_t)iy0 * W_IMG) * C_IMG) + c4;
    const float4* __restrict__ row1 =
        (const float4*)(img + ((size_t)iy1 * W_IMG) * C_IMG) + c4;

    // x axis scalars (uniform)
    const float wf  = (float)rw;
    const float sfx = wf * (1.0f / POOL);
    const float xcl = fmaxf(wf - 1.0f, 0.0f);

    float4* __restrict__ optr =
        (float4*)out + ((size_t)(r * POOL + py) * POOL) * CPP + c4;

    // Prologue: coords + loads for px=0.
    int o0, o1;
    float wx;
    xcoords(0, sfx, xcl, rx, rw, o0, o1, wx);
    float4 v00 = __ldg(row0 + o0);
    float4 v01 = __ldg(row0 + o1);
    float4 v10 = __ldg(row1 + o0);
    float4 v11 = __ldg(row1 + o1);

    #pragma unroll
    for (int px = 0; px < POOL; ++px) {
        // Lookahead: compute px+1 coords and issue its loads before math of px.
        float4 n00, n01, n10, n11;
        float wx_n = 0.0f;
        if (px + 1 < POOL) {
            int p0, p1;
            xcoords(px + 1, sfx, xcl, rx, rw, p0, p1, wx_n);
            n00 = __ldg(row0 + p0);
            n01 = __ldg(row0 + p1);
            n10 = __ldg(row1 + p0);
            n11 = __ldg(row1 + p1);
        }

        const float wx1 = 1.0f - wx;
        float4 o;
        o.x = (v00.x * wx1 + v01.x * wx) * wy1 + (v10.x * wx1 + v11.x * wx) * wy;
        o.y = (v00.y * wx1 + v01.y * wx) * wy1 + (v10.y * wx1 + v11.y * wx) * wy;
        o.z = (v00.z * wx1 + v01.z * wx) * wy1 + (v10.z * wx1 + v11.z * wx) * wy;
        o.w = (v00.w * wx1 + v01.w * wx) * wy1 + (v10.w * wx1 + v11.w * wx) * wy;

        __stcs(optr + (size_t)px * CPP, o);

        v00 = n00; v01 = n01; v10 = n10; v11 = n11;
        wx = wx_n;
    }
}

extern "C" void kernel_launch(void* const* d_in, const int* in_sizes, int n_in,
                              void* d_out, int out_size)
{
    const float* img  = (const float*)d_in[0];
    const int*   rois = (const int*)d_in[1];
    float*       out  = (float*)d_out;

    dim3 grid(NUM_ROIS * POOL);
    dim3 block(256);
    roi_pool_kernel<<<grid, block>>>(img, rois, out);
}

// round 8
// speedup vs baseline: 1.1368x; 1.0349x over previous
#include <cuda_runtime.h>
#include <cuda_bf16.h>
#include <cstdint>

// ROI pooling (crop + 7x7 bilinear resize), NHWC.
// img:  (1, 128, 128, 1024) fp32
// rois: (1, 1000, 4) int32  -> {x, y, w, h}
// out:  (1, 1000, 7, 7, 1024) fp32
//
// One CTA per (roi, py); 256 threads x float4 covers C=1024.
// R5 structure (precomputed per-px offsets/weights, 1-px load lookahead)
// with packed f32x2 math: 8 ops per float4 instead of 16 FFMA.

#define H_IMG 128
#define W_IMG 128
#define C_IMG 1024
#define POOL 7
#define NUM_ROIS 1000
#define CPP (C_IMG / 4)   // float4s per pixel = 256

__device__ __forceinline__ uint64_t pack2(float v) {
    uint64_t r;
    asm("mov.b64 %0, {%1, %1};" : "=l"(r) : "f"(v));
    return r;
}
__device__ __forceinline__ uint64_t mul2(uint64_t a, uint64_t b) {
    uint64_t r;
    asm("mul.rn.f32x2 %0, %1, %2;" : "=l"(r) : "l"(a), "l"(b));
    return r;
}
__device__ __forceinline__ uint64_t fma2(uint64_t a, uint64_t b, uint64_t c) {
    uint64_t r;
    asm("fma.rn.f32x2 %0, %1, %2, %3;" : "=l"(r) : "l"(a), "l"(b), "l"(c));
    return r;
}

union F4P2 {
    float4 f4;
    uint64_t u2[2];
};

__global__ __launch_bounds__(256, 4)
void roi_pool_kernel(const float* __restrict__ img,
                     const int*   __restrict__ rois,
                     float*       __restrict__ out)
{
    const int b  = blockIdx.x;            // 0 .. 6999
    const int py = b % POOL;
    const int r  = b / POOL;
    const int c4 = threadIdx.x;           // float4 channel index, 0..255

    const int4 roi = __ldg(((const int4*)rois) + r);
    const int rx = roi.x, ry = roi.y, rw = roi.z, rh = roi.w;

    // y axis (uniform across CTA)
    const float hf = (float)rh;
    float fy = (py + 0.5f) * (hf * (1.0f / POOL)) - 0.5f;
    fy = fminf(fmaxf(fy, 0.0f), fmaxf(hf - 1.0f, 0.0f));
    int   iy0 = (int)floorf(fy);
    const float wy  = fy - (float)iy0;
    const float wy1 = 1.0f - wy;
    int   iy1 = min(iy0 + 1, rh - 1);
    iy0 += ry;  iy1 += ry;

    const float4* __restrict__ row0 =
        (const float4*)(img + ((size_t)iy0 * W_IMG) * C_IMG) + c4;
    const float4* __restrict__ row1 =
        (const float4*)(img + ((size_t)iy1 * W_IMG) * C_IMG) + c4;

    // x axis scalars (uniform)
    const float wf  = (float)rw;
    const float sfx = wf * (1.0f / POOL);
    const float xcl = fmaxf(wf - 1.0f, 0.0f);

    // Precompute per-px column offsets and the 4 bilinear weights (all uniform).
    int   o0[POOL], o1[POOL];
    float w00[POOL], w01[POOL], w10[POOL], w11[POOL];
    #pragma unroll
    for (int px = 0; px < POOL; ++px) {
        float fx = (px + 0.5f) * sfx - 0.5f;
        fx = fminf(fmaxf(fx, 0.0f), xcl);
        int   ix0 = (int)floorf(fx);
        const float wx  = fx - (float)ix0;
        const float wx1 = 1.0f - wx;
        int   ix1 = min(ix0 + 1, rw - 1);
        o0[px] = (rx + ix0) * CPP;
        o1[px] = (rx + ix1) * CPP;
        w00[px] = wx1 * wy1;
        w01[px] = wx  * wy1;
        w10[px] = wx1 * wy;
        w11[px] = wx  * wy;
    }

    float4* __restrict__ optr =
        (float4*)out + ((size_t)(r * POOL + py) * POOL) * CPP + c4;

    // Software-pipelined px loop: loads for px+1 issue before math of px.
    F4P2 v00, v01, v10, v11;
    v00.f4 = __ldg(row0 + o0[0]);
    v01.f4 = __ldg(row0 + o1[0]);
    v10.f4 = __ldg(row1 + o0[0]);
    v11.f4 = __ldg(row1 + o1[0]);

    #pragma unroll
    for (int px = 0; px < POOL; ++px) {
        F4P2 n00, n01, n10, n11;
        if (px + 1 < POOL) {
            n00.f4 = __ldg(row0 + o0[px + 1]);
            n01.f4 = __ldg(row0 + o1[px + 1]);
            n10.f4 = __ldg(row1 + o0[px + 1]);
            n11.f4 = __ldg(row1 + o1[px + 1]);
        }

        const uint64_t aa = pack2(w00[px]);
        const uint64_t bb = pack2(w01[px]);
        const uint64_t cc = pack2(w10[px]);
        const uint64_t dd = pack2(w11[px]);

        F4P2 o;
        o.u2[0] = fma2(v11.u2[0], dd,
                  fma2(v10.u2[0], cc,
                  fma2(v01.u2[0], bb,
                  mul2(v00.u2[0], aa))));
        o.u2[1] = fma2(v11.u2[1], dd,
                  fma2(v10.u2[1], cc,
                  fma2(v01.u2[1], bb,
                  mul2(v00.u2[1], aa))));

        __stcs(optr + (size_t)px * CPP, o.f4);

        v00 = n00; v01 = n01; v10 = n10; v11 = n11;
    }
}

extern "C" void kernel_launch(void* const* d_in, const int* in_sizes, int n_in,
                              void* d_out, int out_size)
{
    const float* img  = (const float*)d_in[0];
    const int*   rois = (const int*)d_in[1];
    float*       out  = (float*)d_out;

    dim3 grid(NUM_ROIS * POOL);
    dim3 block(256);
    roi_pool_kernel<<<grid, block>>>(img, rois, out);
}

// round 9
// speedup vs baseline: 1.1467x; 1.0087x over previous
#include <cuda_runtime.h>
#include <cuda_bf16.h>

// ROI pooling (crop + 7x7 bilinear resize), NHWC.
// img:  (1, 128, 128, 1024) fp32
// rois: (1, 1000, 4) int32  -> {x, y, w, h}
// out:  (1, 1000, 7, 7, 1024) fp32
//
// One CTA per (roi, py); 256 threads x float4 covers C=1024.
// Precomputed per-px offsets/weights + TWO-px load lookahead:
// 12 independent LDG.128 in flight per thread (3 CTAs/SM, ~84-reg budget).

#define H_IMG 128
#define W_IMG 128
#define C_IMG 1024
#define POOL 7
#define NUM_ROIS 1000
#define CPP (C_IMG / 4)   // float4s per pixel = 256

__global__ __launch_bounds__(256, 3)
void roi_pool_kernel(const float* __restrict__ img,
                     const int*   __restrict__ rois,
                     float*       __restrict__ out)
{
    const int b  = blockIdx.x;            // 0 .. 6999
    const int py = b % POOL;
    const int r  = b / POOL;
    const int c4 = threadIdx.x;           // float4 channel index, 0..255

    const int4 roi = __ldg(((const int4*)rois) + r);
    const int rx = roi.x, ry = roi.y, rw = roi.z, rh = roi.w;

    // y axis (uniform across CTA)
    const float hf = (float)rh;
    float fy = (py + 0.5f) * (hf * (1.0f / POOL)) - 0.5f;
    fy = fminf(fmaxf(fy, 0.0f), fmaxf(hf - 1.0f, 0.0f));
    int   iy0 = (int)floorf(fy);
    const float wy  = fy - (float)iy0;
    const float wy1 = 1.0f - wy;
    int   iy1 = min(iy0 + 1, rh - 1);
    iy0 += ry;  iy1 += ry;

    const float4* __restrict__ row0 =
        (const float4*)(img + ((size_t)iy0 * W_IMG) * C_IMG) + c4;
    const float4* __restrict__ row1 =
        (const float4*)(img + ((size_t)iy1 * W_IMG) * C_IMG) + c4;

    // x axis scalars (uniform)
    const float wf  = (float)rw;
    const float sfx = wf * (1.0f / POOL);
    const float xcl = fmaxf(wf - 1.0f, 0.0f);

    // Precompute per-px column offsets and the 4 bilinear weights (all uniform).
    int   o0[POOL], o1[POOL];
    float w00[POOL], w01[POOL], w10[POOL], w11[POOL];
    #pragma unroll
    for (int px = 0; px < POOL; ++px) {
        float fx = (px + 0.5f) * sfx - 0.5f;
        fx = fminf(fmaxf(fx, 0.0f), xcl);
        int   ix0 = (int)floorf(fx);
        const float wx  = fx - (float)ix0;
        const float wx1 = 1.0f - wx;
        int   ix1 = min(ix0 + 1, rw - 1);
        o0[px] = (rx + ix0) * CPP;
        o1[px] = (rx + ix1) * CPP;
        w00[px] = wx1 * wy1;
        w01[px] = wx  * wy1;
        w10[px] = wx1 * wy;
        w11[px] = wx  * wy;
    }

    float4* __restrict__ optr =
        (float4*)out + ((size_t)(r * POOL + py) * POOL) * CPP + c4;

    // Software-pipelined px loop, depth 2: loads for px+2 issue before math of px.
    float4 a00 = __ldg(row0 + o0[0]);
    float4 a01 = __ldg(row0 + o1[0]);
    float4 a10 = __ldg(row1 + o0[0]);
    float4 a11 = __ldg(row1 + o1[0]);

    float4 b00 = __ldg(row0 + o0[1]);
    float4 b01 = __ldg(row0 + o1[1]);
    float4 b10 = __ldg(row1 + o0[1]);
    float4 b11 = __ldg(row1 + o1[1]);

    #pragma unroll
    for (int px = 0; px < POOL; ++px) {
        float4 n00, n01, n10, n11;
        if (px + 2 < POOL) {
            n00 = __ldg(row0 + o0[px + 2]);
            n01 = __ldg(row0 + o1[px + 2]);
            n10 = __ldg(row1 + o0[px + 2]);
            n11 = __ldg(row1 + o1[px + 2]);
        }

        const float a = w00[px], bb = w01[px];
        const float c = w10[px], d  = w11[px];
        float4 o;
        o.x = a00.x * a + a01.x * bb + a10.x * c + a11.x * d;
        o.y = a00.y * a + a01.y * bb + a10.y * c + a11.y * d;
        o.z = a00.z * a + a01.z * bb + a10.z * c + a11.z * d;
        o.w = a00.w * a + a01.w * bb + a10.w * c + a11.w * d;

        __stcs(optr + (size_t)px * CPP, o);

        a00 = b00; a01 = b01; a10 = b10; a11 = b11;
        b00 = n00; b01 = n01; b10 = n10; b11 = n11;
    }
}

extern "C" void kernel_launch(void* const* d_in, const int* in_sizes, int n_in,
                              void* d_out, int out_size)
{
    const float* img  = (const float*)d_in[0];
    const int*   rois = (const int*)d_in[1];
    float*       out  = (float*)d_out;

    dim3 grid(NUM_ROIS * POOL);
    dim3 block(256);
    roi_pool_kernel<<<grid, block>>>(img, rois, out);
}

// round 10
// speedup vs baseline: 1.1473x; 1.0006x over previous
#include <cuda_runtime.h>
#include <cuda_bf16.h>
#include <cstdint>

// ROI pooling (crop + 7x7 bilinear resize), NHWC.
// img:  (1, 128, 128, 1024) fp32
// rois: (1, 1000, 4) int32  -> {x, y, w, h}
// out:  (1, 1000, 7, 7, 1024) fp32
//
// One CTA per (roi, py); 256 threads x float4 covers C=1024.
// R5 structure with a register diet: per-px column offsets packed 2x16-bit
// into one int (unpack = 2 ALU ops in the address path), weights held as
// wx[7] + wy scalars with 2-level lerp. Frees ~20 regs for deeper load
// batching at the same occupancy.

#define H_IMG 128
#define W_IMG 128
#define C_IMG 1024
#define POOL 7
#define NUM_ROIS 1000
#define CPP (C_IMG / 4)   // float4s per pixel = 256

__global__ __launch_bounds__(256, 4)
void roi_pool_kernel(const float* __restrict__ img,
                     const int*   __restrict__ rois,
                     float*       __restrict__ out)
{
    const int b  = blockIdx.x;            // 0 .. 6999
    const int py = b % POOL;
    const int r  = b / POOL;
    const int c4 = threadIdx.x;           // float4 channel index, 0..255

    const int4 roi = __ldg(((const int4*)rois) + r);
    const int rx = roi.x, ry = roi.y, rw = roi.z, rh = roi.w;

    // y axis (uniform across CTA)
    const float hf = (float)rh;
    float fy = (py + 0.5f) * (hf * (1.0f / POOL)) - 0.5f;
    fy = fminf(fmaxf(fy, 0.0f), fmaxf(hf - 1.0f, 0.0f));
    int   iy0 = (int)floorf(fy);
    const float wy  = fy - (float)iy0;
    const float wy1 = 1.0f - wy;
    int   iy1 = min(iy0 + 1, rh - 1);
    iy0 += ry;  iy1 += ry;

    const float4* __restrict__ row0 =
        (const float4*)(img + ((size_t)iy0 * W_IMG) * C_IMG) + c4;
    const float4* __restrict__ row1 =
        (const float4*)(img + ((size_t)iy1 * W_IMG) * C_IMG) + c4;

    // x axis scalars (uniform)
    const float wf  = (float)rw;
    const float sfx = wf * (1.0f / POOL);
    const float xcl = fmaxf(wf - 1.0f, 0.0f);

    // Precompute per-px packed offsets (two 16-bit float4-unit offsets) and wx.
    uint32_t pp[POOL];
    float    wxs[POOL];
    #pragma unroll
    for (int px = 0; px < POOL; ++px) {
        float fx = (px + 0.5f) * sfx - 0.5f;
        fx = fminf(fmaxf(fx, 0.0f), xcl);
        int   ix0 = (int)floorf(fx);
        wxs[px] = fx - (float)ix0;
        int   ix1 = min(ix0 + 1, rw - 1);
        const uint32_t o0 = (uint32_t)((rx + ix0) * CPP);   // <= 32512
        const uint32_t o1 = (uint32_t)((rx + ix1) * CPP);
        pp[px] = o0 | (o1 << 16);
    }

    float4* __restrict__ optr =
        (float4*)out + ((size_t)(r * POOL + py) * POOL) * CPP + c4;

    // Software-pipelined px loop: loads for px+1 issue before math of px.
    uint32_t p = pp[0];
    float4 v00 = __ldg(row0 + (p & 0xFFFFu));
    float4 v01 = __ldg(row0 + (p >> 16));
    float4 v10 = __ldg(row1 + (p & 0xFFFFu));
    float4 v11 = __ldg(row1 + (p >> 16));

    #pragma unroll
    for (int px = 0; px < POOL; ++px) {
        float4 n00, n01, n10, n11;
        if (px + 1 < POOL) {
            const uint32_t q  = pp[px + 1];
            const uint32_t q0 = q & 0xFFFFu;
            const uint32_t q1 = q >> 16;
            n00 = __ldg(row0 + q0);
            n01 = __ldg(row0 + q1);
            n10 = __ldg(row1 + q0);
            n11 = __ldg(row1 + q1);
        }

        const float wx  = wxs[px];
        const float wx1 = 1.0f - wx;
        float4 o;
        o.x = (v00.x * wx1 + v01.x * wx) * wy1 + (v10.x * wx1 + v11.x * wx) * wy;
        o.y = (v00.y * wx1 + v01.y * wx) * wy1 + (v10.y * wx1 + v11.y * wx) * wy;
        o.z = (v00.z * wx1 + v01.z * wx) * wy1 + (v10.z * wx1 + v11.z * wx) * wy;
        o.w = (v00.w * wx1 + v01.w * wx) * wy1 + (v10.w * wx1 + v11.w * wx) * wy;

        __stcs(optr + (size_t)px * CPP, o);

        v00 = n00; v01 = n01; v10 = n10; v11 = n11;
    }
}

extern "C" void kernel_launch(void* const* d_in, const int* in_sizes, int n_in,
                              void* d_out, int out_size)
{
    const float* img  = (const float*)d_in[0];
    const int*   rois = (const int*)d_in[1];
    float*       out  = (float*)d_out;

    dim3 grid(NUM_ROIS * POOL);
    dim3 block(256);
    roi_pool_kernel<<<grid, block>>>(img, rois, out);
}

// round 11
// speedup vs baseline: 1.1914x; 1.0384x over previous
#include <cuda_runtime.h>
#include <cuda_bf16.h>

// ROI pooling (crop + 7x7 bilinear resize), NHWC.
// img:  (1, 128, 128, 1024) fp32
// rois: (1, 1000, 4) int32  -> {x, y, w, h}
// out:  (1, 1000, 7, 7, 1024) fp32
//
// R5 champion structure (precomputed per-px offsets + 4 weights, 1-px load
// lookahead, __stcs) at finer CTA granularity: 128-thread CTAs, grid (7000,2),
// blockIdx.y picks the channel half. 8 CTAs/SM -> desynchronized load bursts.

#define H_IMG 128
#define W_IMG 128
#define C_IMG 1024
#define POOL 7
#define NUM_ROIS 1000
#define CPP (C_IMG / 4)   // float4s per pixel = 256

__global__ __launch_bounds__(128, 8)
void roi_pool_kernel(const float* __restrict__ img,
                     const int*   __restrict__ rois,
                     float*       __restrict__ out)
{
    const int b  = blockIdx.x;            // 0 .. 6999
    const int py = b % POOL;
    const int r  = b / POOL;
    const int c4 = threadIdx.x + (blockIdx.y << 7);   // 0..255 float4 channel

    const int4 roi = __ldg(((const int4*)rois) + r);
    const int rx = roi.x, ry = roi.y, rw = roi.z, rh = roi.w;

    // y axis (uniform across CTA)
    const float hf = (float)rh;
    float fy = (py + 0.5f) * (hf * (1.0f / POOL)) - 0.5f;
    fy = fminf(fmaxf(fy, 0.0f), fmaxf(hf - 1.0f, 0.0f));
    int   iy0 = (int)floorf(fy);
    const float wy  = fy - (float)iy0;
    const float wy1 = 1.0f - wy;
    int   iy1 = min(iy0 + 1, rh - 1);
    iy0 += ry;  iy1 += ry;

    const float4* __restrict__ row0 =
        (const float4*)(img + ((size_t)iy0 * W_IMG) * C_IMG) + c4;
    const float4* __restrict__ row1 =
        (const float4*)(img + ((size_t)iy1 * W_IMG) * C_IMG) + c4;

    // x axis scalars (uniform)
    const float wf  = (float)rw;
    const float sfx = wf * (1.0f / POOL);
    const float xcl = fmaxf(wf - 1.0f, 0.0f);

    // Precompute per-px column offsets and the 4 bilinear weights (all uniform).
    int   o0[POOL], o1[POOL];
    float w00[POOL], w01[POOL], w10[POOL], w11[POOL];
    #pragma unroll
    for (int px = 0; px < POOL; ++px) {
        float fx = (px + 0.5f) * sfx - 0.5f;
        fx = fminf(fmaxf(fx, 0.0f), xcl);
        int   ix0 = (int)floorf(fx);
        const float wx  = fx - (float)ix0;
        const float wx1 = 1.0f - wx;
        int   ix1 = min(ix0 + 1, rw - 1);
        o0[px] = (rx + ix0) * CPP;
        o1[px] = (rx + ix1) * CPP;
        w00[px] = wx1 * wy1;
        w01[px] = wx  * wy1;
        w10[px] = wx1 * wy;
        w11[px] = wx  * wy;
    }

    float4* __restrict__ optr =
        (float4*)out + ((size_t)(r * POOL + py) * POOL) * CPP + c4;

    // Software-pipelined px loop: loads for px+1 issue before math of px.
    float4 v00 = __ldg(row0 + o0[0]);
    float4 v01 = __ldg(row0 + o1[0]);
    float4 v10 = __ldg(row1 + o0[0]);
    float4 v11 = __ldg(row1 + o1[0]);

    #pragma unroll
    for (int px = 0; px < POOL; ++px) {
        float4 n00, n01, n10, n11;
        if (px + 1 < POOL) {
            const int p0 = o0[px + 1], p1 = o1[px + 1];
            n00 = __ldg(row0 + p0);
            n01 = __ldg(row0 + p1);
            n10 = __ldg(row1 + p0);
            n11 = __ldg(row1 + p1);
        }

        const float a = w00[px], bb = w01[px];
        const float c = w10[px], d  = w11[px];
        float4 o;
        o.x = v00.x * a + v01.x * bb + v10.x * c + v11.x * d;
        o.y = v00.y * a + v01.y * bb + v10.y * c + v11.y * d;
        o.z = v00.z * a + v01.z * bb + v10.z * c + v11.z * d;
        o.w = v00.w * a + v01.w * bb + v10.w * c + v11.w * d;

        __stcs(optr + (size_t)px * CPP, o);

        v00 = n00; v01 = n01; v10 = n10; v11 = n11;
    }
}

extern "C" void kernel_launch(void* const* d_in, const int* in_sizes, int n_in,
                              void* d_out, int out_size)
{
    const float* img  = (const float*)d_in[0];
    const int*   rois = (const int*)d_in[1];
    float*       out  = (float*)d_out;

    dim3 grid(NUM_ROIS * POOL, 2);
    dim3 block(128);
    roi_pool_kernel<<<grid, block>>>(img, rois, out);
}